// round 2
// baseline (speedup 1.0000x reference)
#include <cuda_runtime.h>
#include <cstddef>

#define BB 4
#define SS 2048
#define DD 512
#define HH 8
#define DH 64
#define MTOT (BB * SS)

// Scratch (allocation-free rule: __device__ globals)
__device__ float g_Q[MTOT * DD];
__device__ float g_K[MTOT * DD];
__device__ float g_V[MTOT * DD];
__device__ float g_A[MTOT * DD];

// ---------------------------------------------------------------------------
// C[M,N] = A[M,K] @ W[N,K]^T + bias[N]
// 128x128 tile, BK=16, 256 threads, 8x8 microtile.
// ---------------------------------------------------------------------------
__global__ __launch_bounds__(256) void gemm_bias(
    const float* __restrict__ A, const float* __restrict__ W,
    const float* __restrict__ bias, float* __restrict__ C,
    int M, int N, int K)
{
    __shared__ float As[16][132];   // [k][m]
    __shared__ float Ws[16][132];   // [k][n]

    const int tid = threadIdx.x;
    const int bm = blockIdx.y * 128;
    const int bn = blockIdx.x * 128;
    const int tx = tid & 15;        // n-tile
    const int ty = tid >> 4;        // m-tile
    const int lr = tid >> 2;        // 0..63 row for loads
    const int lq = (tid & 3) * 4;   // 0,4,8,12 k-offset for loads

    float acc[8][8];
#pragma unroll
    for (int i = 0; i < 8; i++)
#pragma unroll
        for (int j = 0; j < 8; j++) acc[i][j] = 0.f;

    for (int k0 = 0; k0 < K; k0 += 16) {
        float4 a0 = *(const float4*)&A[(size_t)(bm + lr) * K + k0 + lq];
        float4 a1 = *(const float4*)&A[(size_t)(bm + lr + 64) * K + k0 + lq];
        float4 w0 = *(const float4*)&W[(size_t)(bn + lr) * K + k0 + lq];
        float4 w1 = *(const float4*)&W[(size_t)(bn + lr + 64) * K + k0 + lq];

        As[lq + 0][lr] = a0.x; As[lq + 1][lr] = a0.y;
        As[lq + 2][lr] = a0.z; As[lq + 3][lr] = a0.w;
        As[lq + 0][lr + 64] = a1.x; As[lq + 1][lr + 64] = a1.y;
        As[lq + 2][lr + 64] = a1.z; As[lq + 3][lr + 64] = a1.w;
        Ws[lq + 0][lr] = w0.x; Ws[lq + 1][lr] = w0.y;
        Ws[lq + 2][lr] = w0.z; Ws[lq + 3][lr] = w0.w;
        Ws[lq + 0][lr + 64] = w1.x; Ws[lq + 1][lr + 64] = w1.y;
        Ws[lq + 2][lr + 64] = w1.z; Ws[lq + 3][lr + 64] = w1.w;

        __syncthreads();

#pragma unroll
        for (int kk = 0; kk < 16; kk++) {
            float af[8], wf[8];
            *(float4*)&af[0] = *(float4*)&As[kk][ty * 8];
            *(float4*)&af[4] = *(float4*)&As[kk][ty * 8 + 4];
            *(float4*)&wf[0] = *(float4*)&Ws[kk][tx * 8];
            *(float4*)&wf[4] = *(float4*)&Ws[kk][tx * 8 + 4];
#pragma unroll
            for (int i = 0; i < 8; i++)
#pragma unroll
                for (int j = 0; j < 8; j++) acc[i][j] += af[i] * wf[j];
        }
        __syncthreads();
    }

#pragma unroll
    for (int i = 0; i < 8; i++) {
        const int row = bm + ty * 8 + i;
#pragma unroll
        for (int j = 0; j < 8; j += 4) {
            float4 v;
            v.x = acc[i][j + 0] + bias[bn + tx * 8 + j + 0];
            v.y = acc[i][j + 1] + bias[bn + tx * 8 + j + 1];
            v.z = acc[i][j + 2] + bias[bn + tx * 8 + j + 2];
            v.w = acc[i][j + 3] + bias[bn + tx * 8 + j + 3];
            *(float4*)&C[(size_t)row * N + bn + tx * 8 + j] = v;
        }
    }
}

// ---------------------------------------------------------------------------
// Causal flash attention. Grid (S/64, H, B), 256 threads.
// Q,K,V layout: [B,S,D] with head h at cols h*64..h*64+63.
// ---------------------------------------------------------------------------
__global__ __launch_bounds__(256) void attn_kernel(
    const float* __restrict__ Q, const float* __restrict__ K,
    const float* __restrict__ V, float* __restrict__ O)
{
    __shared__ float Qs[64][68];
    __shared__ float Ks[64][68];   // reused for V
    __shared__ float Ps[64][68];   // scores / probabilities
    __shared__ float m_s[64], l_s[64], al_s[64];

    const int tid = threadIdx.x;
    const int qb = blockIdx.x, h = blockIdx.y, b = blockIdx.z;
    const int q0 = qb * 64;
    const size_t baseQ  = ((size_t)b * SS + q0) * DD + h * DH;
    const size_t baseBH = ((size_t)b * SS) * DD + h * DH;

    const int lr = tid >> 4;          // 0..15
    const int lc = (tid & 15) * 4;    // 0..60
    const int tx = tid & 15;
    const int ty = tid >> 4;

    // Load Q tile
#pragma unroll
    for (int rr = lr; rr < 64; rr += 16)
        *(float4*)&Qs[rr][lc] = *(const float4*)&Q[baseQ + (size_t)rr * DD + lc];
    if (tid < 64) { m_s[tid] = -1e30f; l_s[tid] = 0.f; }

    float acc[4][4];
#pragma unroll
    for (int i = 0; i < 4; i++)
#pragma unroll
        for (int j = 0; j < 4; j++) acc[i][j] = 0.f;

    __syncthreads();

    for (int kb = 0; kb <= qb; kb++) {
        const int k0 = kb * 64;
        // Load K tile
#pragma unroll
        for (int rr = lr; rr < 64; rr += 16)
            *(float4*)&Ks[rr][lc] =
                *(const float4*)&K[baseBH + (size_t)(k0 + rr) * DD + lc];
        __syncthreads();

        // Scores: sc[i][j] = sum_d Qs[ty*4+i][d] * Ks[tx*4+j][d]
        float sc[4][4];
#pragma unroll
        for (int i = 0; i < 4; i++)
#pragma unroll
            for (int j = 0; j < 4; j++) sc[i][j] = 0.f;
#pragma unroll 8
        for (int d = 0; d < 64; d++) {
            float qf[4], kf[4];
#pragma unroll
            for (int i = 0; i < 4; i++) qf[i] = Qs[ty * 4 + i][d];
#pragma unroll
            for (int j = 0; j < 4; j++) kf[j] = Ks[tx * 4 + j][d];
#pragma unroll
            for (int i = 0; i < 4; i++)
#pragma unroll
                for (int j = 0; j < 4; j++) sc[i][j] += qf[i] * kf[j];
        }
        const bool diag = (kb == qb);
#pragma unroll
        for (int i = 0; i < 4; i++)
#pragma unroll
            for (int j = 0; j < 4; j++) {
                float v = sc[i][j] * 0.125f;
                if (diag && (tx * 4 + j > ty * 4 + i)) v = -1e9f;
                Ps[ty * 4 + i][tx * 4 + j] = v;
            }
        __syncthreads();

        // Online softmax: 4 threads per row (quad), 16 cols each
        {
            const int r = tid >> 2;
            const int cb = (tid & 3) * 16;
            float mx = -1e30f;
#pragma unroll
            for (int c = 0; c < 16; c++) mx = fmaxf(mx, Ps[r][cb + c]);
            mx = fmaxf(mx, __shfl_xor_sync(0xffffffffu, mx, 1));
            mx = fmaxf(mx, __shfl_xor_sync(0xffffffffu, mx, 2));
            const float mold = m_s[r];
            const float mnew = fmaxf(mold, mx);
            float sum = 0.f;
#pragma unroll
            for (int c = 0; c < 16; c++) {
                float p = __expf(Ps[r][cb + c] - mnew);
                Ps[r][cb + c] = p;
                sum += p;
            }
            sum += __shfl_xor_sync(0xffffffffu, sum, 1);
            sum += __shfl_xor_sync(0xffffffffu, sum, 2);
            if ((tid & 3) == 0) {
                const float alpha = __expf(mold - mnew);
                l_s[r] = l_s[r] * alpha + sum;
                m_s[r] = mnew;
                al_s[r] = alpha;
            }
        }
        // Load V tile into Ks (safe: scores done, sync'd above)
#pragma unroll
        for (int rr = lr; rr < 64; rr += 16)
            *(float4*)&Ks[rr][lc] =
                *(const float4*)&V[baseBH + (size_t)(k0 + rr) * DD + lc];
        __syncthreads();

        // O update
        float ar[4];
#pragma unroll
        for (int i = 0; i < 4; i++) ar[i] = al_s[ty * 4 + i];
#pragma unroll
        for (int i = 0; i < 4; i++)
#pragma unroll
            for (int j = 0; j < 4; j++) acc[i][j] *= ar[i];
#pragma unroll 8
        for (int k = 0; k < 64; k++) {
            float4 vf = *(float4*)&Ks[k][tx * 4];
            float pf[4];
#pragma unroll
            for (int i = 0; i < 4; i++) pf[i] = Ps[ty * 4 + i][k];
#pragma unroll
            for (int i = 0; i < 4; i++) {
                acc[i][0] += pf[i] * vf.x;
                acc[i][1] += pf[i] * vf.y;
                acc[i][2] += pf[i] * vf.z;
                acc[i][3] += pf[i] * vf.w;
            }
        }
        __syncthreads();
    }

    // Epilogue: normalize and write
#pragma unroll
    for (int i = 0; i < 4; i++) {
        const int row = q0 + ty * 4 + i;
        const float inv = 1.f / l_s[ty * 4 + i];
        float4 v;
        v.x = acc[i][0] * inv; v.y = acc[i][1] * inv;
        v.z = acc[i][2] * inv; v.w = acc[i][3] * inv;
        *(float4*)&O[((size_t)b * SS + row) * DD + h * DH + tx * 4] = v;
    }
}

// ---------------------------------------------------------------------------
extern "C" void kernel_launch(void* const* d_in, const int* in_sizes, int n_in,
                              void* d_out, int out_size)
{
    const float* x  = (const float*)d_in[0];
    // d_in[1] is the causal mask -- implicit in the attention kernel
    const float* WQ = (const float*)d_in[2];
    const float* bQ = (const float*)d_in[3];
    const float* WK = (const float*)d_in[4];
    const float* bK = (const float*)d_in[5];
    const float* WV = (const float*)d_in[6];
    const float* bV = (const float*)d_in[7];
    const float* WO = (const float*)d_in[8];
    const float* bO = (const float*)d_in[9];
    float* out = (float*)d_out;

    float *Qp, *Kp, *Vp, *Ap;
    cudaGetSymbolAddress((void**)&Qp, g_Q);
    cudaGetSymbolAddress((void**)&Kp, g_K);
    cudaGetSymbolAddress((void**)&Vp, g_V);
    cudaGetSymbolAddress((void**)&Ap, g_A);

    dim3 gg(DD / 128, MTOT / 128);   // (4, 64)
    gemm_bias<<<gg, 256>>>(x, WQ, bQ, Qp, MTOT, DD, DD);
    gemm_bias<<<gg, 256>>>(x, WK, bK, Kp, MTOT, DD, DD);
    gemm_bias<<<gg, 256>>>(x, WV, bV, Vp, MTOT, DD, DD);
    attn_kernel<<<dim3(SS / 64, HH, BB), 256>>>(Qp, Kp, Vp, Ap);
    gemm_bias<<<gg, 256>>>(Ap, WO, bO, out, MTOT, DD, DD);
}

// round 6
// speedup vs baseline: 3.7381x; 3.7381x over previous
#include <cuda_runtime.h>
#include <cuda_fp16.h>
#include <cstdint>
#include <cstddef>

#define BB 4
#define SS 2048
#define DD 512
#define HH 8
#define DH 64
#define MTOT (BB * SS)

// softmax scale folded with log2(e):  scores_log2 = (Q*SCL) . K
#define SCL 0.18033688011112042f   // (1/8) * log2(e)

// Scratch (allocation-free rule: __device__ globals)
__device__ float g_Q[MTOT * DD];
__device__ float g_K[MTOT * DD];
__device__ float g_V[MTOT * DD];
__device__ float g_A[MTOT * DD];

// ===========================================================================
// helpers
// ===========================================================================
__device__ __forceinline__ uint32_t smem_u32(const void* p) {
    uint32_t a;
    asm("{ .reg .u64 t; cvta.to.shared.u64 t, %1; cvt.u32.u64 %0, t; }"
        : "=r"(a) : "l"(p));
    return a;
}

__device__ __forceinline__ void ldsm4(uint32_t* r, uint32_t addr) {
    asm volatile("ldmatrix.sync.aligned.m8n8.x4.shared.b16 {%0,%1,%2,%3}, [%4];"
        : "=r"(r[0]), "=r"(r[1]), "=r"(r[2]), "=r"(r[3]) : "r"(addr));
}
__device__ __forceinline__ void ldsm4t(uint32_t* r, uint32_t addr) {
    asm volatile("ldmatrix.sync.aligned.m8n8.x4.trans.shared.b16 {%0,%1,%2,%3}, [%4];"
        : "=r"(r[0]), "=r"(r[1]), "=r"(r[2]), "=r"(r[3]) : "r"(addr));
}

// D(16x8,f32) += A(16x16 f16, row) * B(16x8 f16, col)
__device__ __forceinline__ void mma_f16(float* c, const uint32_t* a,
                                        uint32_t b0, uint32_t b1) {
    asm volatile(
        "mma.sync.aligned.m16n8k16.row.col.f32.f16.f16.f32 "
        "{%0,%1,%2,%3}, {%4,%5,%6,%7}, {%8,%9}, {%0,%1,%2,%3};"
        : "+f"(c[0]), "+f"(c[1]), "+f"(c[2]), "+f"(c[3])
        : "r"(a[0]), "r"(a[1]), "r"(a[2]), "r"(a[3]), "r"(b0), "r"(b1));
}

__device__ __forceinline__ uint32_t h2u(__half2 h) {
    return *reinterpret_cast<uint32_t*>(&h);
}

// float4 -> fp16 hi + fp16 residual lo (packed half2 words)
__device__ __forceinline__ void cvt_hilo(float4 v, uint32_t& h01, uint32_t& h23,
                                         uint32_t& l01, uint32_t& l23) {
    __half2 a = __floats2half2_rn(v.x, v.y);
    __half2 b = __floats2half2_rn(v.z, v.w);
    float2 fa = __half22float2(a);
    float2 fb = __half22float2(b);
    __half2 la = __floats2half2_rn(v.x - fa.x, v.y - fa.y);
    __half2 lb = __floats2half2_rn(v.z - fb.x, v.w - fb.y);
    h01 = h2u(a); h23 = h2u(b); l01 = h2u(la); l23 = h2u(lb);
}

// 2^x via degree-4 poly on FMA pipe (avoids MUFU throughput wall).
__device__ __forceinline__ float fexp2(float x) {
    x = fmaxf(x, -125.0f);
    float n = rintf(x);
    float f = x - n;
    float p = 0.00961812910f;
    p = fmaf(p, f, 0.0555041087f);
    p = fmaf(p, f, 0.240226507f);
    p = fmaf(p, f, 0.693147180f);
    p = fmaf(p, f, 1.0f);
    int e = (int)n;
    return p * __int_as_float((e + 127) << 23);
}

// ===========================================================================
// Split-fp16 tensor GEMM:  C[M,N] = A[M,512] @ W[N,512]^T + bias
// CTA 128x128, K-chunk 32, 256 threads (8 warps: 2M x 4N), warp tile 64x32.
// smem rows padded to 56 halves (112B): 16B-aligned, ldmatrix conflict-free.
// ===========================================================================
#define GSTR 56
#define GA_H 0
#define GA_L 14336
#define GW_H 28672
#define GW_L 43008
#define GBUF 57344
#define GEMM_SMEM (2 * GBUF)

__global__ __launch_bounds__(256) void gemm_split(
    const float* __restrict__ A, const float* __restrict__ W,
    const float* __restrict__ bias, float* __restrict__ C)
{
    extern __shared__ char sm[];
    const uint32_t smb = smem_u32(sm);
    const int tid = threadIdx.x, lane = tid & 31, wid = tid >> 5;
    const int wm = wid & 1, wn = wid >> 1;
    const int bm = blockIdx.y * 128, bn = blockIdx.x * 128;

    float acc[4][4][4];
#pragma unroll
    for (int i = 0; i < 4; i++)
#pragma unroll
        for (int j = 0; j < 4; j++)
#pragma unroll
            for (int k = 0; k < 4; k++) acc[i][j][k] = 0.f;

    const int lr = tid >> 3;          // 0..31 (+i*32 -> 128 rows)
    const int lseg = tid & 7;         // float4 seg within 32-col chunk

    float4 ra[4], rw[4];
#pragma unroll
    for (int i = 0; i < 4; i++) {
        const int r = lr + i * 32;
        ra[i] = *(const float4*)(A + (size_t)(bm + r) * 512 + lseg * 4);
        rw[i] = *(const float4*)(W + (size_t)(bn + r) * 512 + lseg * 4);
    }

#pragma unroll 1
    for (int c = 0; c < 16; c++) {
        const uint32_t bufb = (uint32_t)(c & 1) * GBUF;
        // stage chunk c (fp16 hi/lo split)
#pragma unroll
        for (int i = 0; i < 4; i++) {
            const int r = lr + i * 32;
            const uint32_t off = (uint32_t)(r * GSTR + lseg * 4) * 2;
            uint32_t h01, h23, l01, l23;
            cvt_hilo(ra[i], h01, h23, l01, l23);
            *(uint32_t*)(sm + bufb + GA_H + off) = h01;
            *(uint32_t*)(sm + bufb + GA_H + off + 4) = h23;
            *(uint32_t*)(sm + bufb + GA_L + off) = l01;
            *(uint32_t*)(sm + bufb + GA_L + off + 4) = l23;
            cvt_hilo(rw[i], h01, h23, l01, l23);
            *(uint32_t*)(sm + bufb + GW_H + off) = h01;
            *(uint32_t*)(sm + bufb + GW_H + off + 4) = h23;
            *(uint32_t*)(sm + bufb + GW_L + off) = l01;
            *(uint32_t*)(sm + bufb + GW_L + off + 4) = l23;
        }
        __syncthreads();
        // prefetch chunk c+1
        if (c < 15) {
#pragma unroll
            for (int i = 0; i < 4; i++) {
                const int r = lr + i * 32;
                ra[i] = *(const float4*)(A + (size_t)(bm + r) * 512 + (c + 1) * 32 + lseg * 4);
                rw[i] = *(const float4*)(W + (size_t)(bn + r) * 512 + (c + 1) * 32 + lseg * 4);
            }
        }
        // compute chunk c: 2 x k16
#pragma unroll
        for (int kc = 0; kc < 2; kc++) {
            uint32_t ah[4][4], al[4][4];
#pragma unroll
            for (int mt = 0; mt < 4; mt++) {
                const uint32_t aaddr = smb + bufb + GA_H +
                    (uint32_t)((wm * 64 + mt * 16 + (lane & 15)) * GSTR +
                               kc * 16 + (lane >> 4) * 8) * 2;
                ldsm4(ah[mt], aaddr);
                ldsm4(al[mt], aaddr + (GA_L - GA_H));
            }
#pragma unroll
            for (int np = 0; np < 2; np++) {
                const uint32_t kaddr = smb + bufb + GW_H +
                    (uint32_t)((wn * 32 + np * 16 + (lane & 7) + ((lane & 16) ? 8 : 0)) * GSTR +
                               kc * 16 + ((lane & 8) ? 8 : 0)) * 2;
                uint32_t bh[4], bl[4];
                ldsm4(bh, kaddr);
                ldsm4(bl, kaddr + (GW_L - GW_H));
#pragma unroll
                for (int mt = 0; mt < 4; mt++) {
                    mma_f16(acc[mt][2 * np], ah[mt], bh[0], bh[1]);
                    mma_f16(acc[mt][2 * np], ah[mt], bl[0], bl[1]);
                    mma_f16(acc[mt][2 * np], al[mt], bh[0], bh[1]);
                    mma_f16(acc[mt][2 * np + 1], ah[mt], bh[2], bh[3]);
                    mma_f16(acc[mt][2 * np + 1], ah[mt], bl[2], bl[3]);
                    mma_f16(acc[mt][2 * np + 1], al[mt], bh[2], bh[3]);
                }
            }
        }
        __syncthreads();
    }

    // epilogue: accumulator fragments straight to gmem (+bias)
#pragma unroll
    for (int nt = 0; nt < 4; nt++) {
        const int col = bn + wn * 32 + nt * 8 + 2 * (lane & 3);
        const float b0 = __ldg(bias + col), b1 = __ldg(bias + col + 1);
#pragma unroll
        for (int mt = 0; mt < 4; mt++) {
            const int row = bm + wm * 64 + mt * 16 + (lane >> 2);
            float2 v0 = {acc[mt][nt][0] + b0, acc[mt][nt][1] + b1};
            float2 v1 = {acc[mt][nt][2] + b0, acc[mt][nt][3] + b1};
            *(float2*)(C + (size_t)row * 512 + col) = v0;
            *(float2*)(C + (size_t)(row + 8) * 512 + col) = v1;
        }
    }
}

// ===========================================================================
// Tensor-core causal flash attention.
// BQ=128, BK=64, Dh=64, 256 thr (8 warps, 16 q-rows each).
// QK^T: 3-product split; softmax on fragments; PV: fp16 P x split V.
// smem rows padded to 72 halves (144B): 16B-aligned, ldmatrix conflict-free.
// ===========================================================================
#define ASTR 72
#define AQ_H 0
#define AQ_L 18432
#define AK_H 36864
#define AK_L 46080
#define AV_H 55296
#define AV_L 64512
#define ATTN_SMEM 73728

__global__ __launch_bounds__(256) void attn_tc(
    const float* __restrict__ Q, const float* __restrict__ K,
    const float* __restrict__ V, float* __restrict__ O)
{
    extern __shared__ char sm[];
    const uint32_t smb = smem_u32(sm);
    const int tid = threadIdx.x, lane = tid & 31, wid = tid >> 5;
    const int qb = (gridDim.x - 1) - blockIdx.x;   // long blocks first
    const int h = blockIdx.y, b = blockIdx.z;
    const int q0 = qb * 128;
    const size_t baseQ = ((size_t)b * SS + q0) * DD + h * DH;
    const size_t baseKV = ((size_t)b * SS) * DD + h * DH;
    const int row0 = wid * 16;

    // Stage Q (pre-scaled by SCL), split hi/lo
#pragma unroll
    for (int i = 0; i < 8; i++) {
        const int idx = tid + i * 256;
        const int r = idx >> 4, dseg = idx & 15;
        float4 v = *(const float4*)(Q + baseQ + (size_t)r * DD + dseg * 4);
        v.x *= SCL; v.y *= SCL; v.z *= SCL; v.w *= SCL;
        uint32_t h01, h23, l01, l23;
        cvt_hilo(v, h01, h23, l01, l23);
        const uint32_t off = (uint32_t)(r * ASTR + dseg * 4) * 2;
        *(uint32_t*)(sm + AQ_H + off) = h01;
        *(uint32_t*)(sm + AQ_H + off + 4) = h23;
        *(uint32_t*)(sm + AQ_L + off) = l01;
        *(uint32_t*)(sm + AQ_L + off + 4) = l23;
    }

    float o[8][4];
#pragma unroll
    for (int i = 0; i < 8; i++)
#pragma unroll
        for (int j = 0; j < 4; j++) o[i][j] = 0.f;
    float m0 = -1e30f, m1 = -1e30f, l0 = 0.f, l1 = 0.f;

    const int kbmax = 2 * qb + 1;
#pragma unroll 1
    for (int kb = 0; kb <= kbmax; kb++) {
        const int k0 = kb * 64;
        // load K,V tiles to regs
        float4 rk[4], rv[4];
#pragma unroll
        for (int i = 0; i < 4; i++) {
            const int idx = tid + i * 256;
            const int r = idx >> 4, dseg = idx & 15;
            rk[i] = *(const float4*)(K + baseKV + (size_t)(k0 + r) * DD + dseg * 4);
            rv[i] = *(const float4*)(V + baseKV + (size_t)(k0 + r) * DD + dseg * 4);
        }
        __syncthreads();   // prior iteration's smem reads done (covers Q stage too)
#pragma unroll
        for (int i = 0; i < 4; i++) {
            const int idx = tid + i * 256;
            const int r = idx >> 4, dseg = idx & 15;
            const uint32_t off = (uint32_t)(r * ASTR + dseg * 4) * 2;
            uint32_t h01, h23, l01, l23;
            cvt_hilo(rk[i], h01, h23, l01, l23);
            *(uint32_t*)(sm + AK_H + off) = h01;
            *(uint32_t*)(sm + AK_H + off + 4) = h23;
            *(uint32_t*)(sm + AK_L + off) = l01;
            *(uint32_t*)(sm + AK_L + off + 4) = l23;
            cvt_hilo(rv[i], h01, h23, l01, l23);
            *(uint32_t*)(sm + AV_H + off) = h01;
            *(uint32_t*)(sm + AV_H + off + 4) = h23;
            *(uint32_t*)(sm + AV_L + off) = l01;
            *(uint32_t*)(sm + AV_L + off + 4) = l23;
        }
        __syncthreads();

        // ---- scores S = (Q*SCL) K^T, 3-product split ----
        float s[8][4];
#pragma unroll
        for (int i = 0; i < 8; i++)
#pragma unroll
            for (int j = 0; j < 4; j++) s[i][j] = 0.f;
#pragma unroll
        for (int kc = 0; kc < 4; kc++) {
            uint32_t qh[4], ql[4];
            const uint32_t qaddr = smb + AQ_H +
                (uint32_t)((row0 + (lane & 15)) * ASTR + kc * 16 + (lane >> 4) * 8) * 2;
            ldsm4(qh, qaddr);
            ldsm4(ql, qaddr + (AQ_L - AQ_H));
#pragma unroll
            for (int np = 0; np < 4; np++) {
                const uint32_t kaddr = smb + AK_H +
                    (uint32_t)((np * 16 + (lane & 7) + ((lane & 16) ? 8 : 0)) * ASTR +
                               kc * 16 + ((lane & 8) ? 8 : 0)) * 2;
                uint32_t bh[4], bl[4];
                ldsm4(bh, kaddr);
                ldsm4(bl, kaddr + (AK_L - AK_H));
                mma_f16(s[2 * np], qh, bh[0], bh[1]);
                mma_f16(s[2 * np], qh, bl[0], bl[1]);
                mma_f16(s[2 * np], ql, bh[0], bh[1]);
                mma_f16(s[2 * np + 1], qh, bh[2], bh[3]);
                mma_f16(s[2 * np + 1], qh, bl[2], bl[3]);
                mma_f16(s[2 * np + 1], ql, bh[2], bh[3]);
            }
        }

        // ---- causal mask (only the last two key blocks intersect diag) ----
        if (kb >= 2 * qb) {
            const int qr = q0 + row0 + (lane >> 2);
#pragma unroll
            for (int nt = 0; nt < 8; nt++) {
                const int cc = k0 + nt * 8 + 2 * (lane & 3);
                if (cc > qr)         s[nt][0] = -1e30f;
                if (cc + 1 > qr)     s[nt][1] = -1e30f;
                if (cc > qr + 8)     s[nt][2] = -1e30f;
                if (cc + 1 > qr + 8) s[nt][3] = -1e30f;
            }
        }

        // ---- online softmax on fragments (log2 domain) ----
        float mx0 = -1e30f, mx1 = -1e30f;
#pragma unroll
        for (int nt = 0; nt < 8; nt++) {
            mx0 = fmaxf(mx0, fmaxf(s[nt][0], s[nt][1]));
            mx1 = fmaxf(mx1, fmaxf(s[nt][2], s[nt][3]));
        }
        mx0 = fmaxf(mx0, __shfl_xor_sync(0xffffffffu, mx0, 1));
        mx0 = fmaxf(mx0, __shfl_xor_sync(0xffffffffu, mx0, 2));
        mx1 = fmaxf(mx1, __shfl_xor_sync(0xffffffffu, mx1, 1));
        mx1 = fmaxf(mx1, __shfl_xor_sync(0xffffffffu, mx1, 2));
        const float mn0 = fmaxf(m0, mx0), mn1 = fmaxf(m1, mx1);
        const float a0 = fexp2(m0 - mn0), a1 = fexp2(m1 - mn1);
        m0 = mn0; m1 = mn1;
        float rs0 = 0.f, rs1 = 0.f;
#pragma unroll
        for (int nt = 0; nt < 8; nt++) {
            s[nt][0] = fexp2(s[nt][0] - mn0);
            s[nt][1] = fexp2(s[nt][1] - mn0);
            s[nt][2] = fexp2(s[nt][2] - mn1);
            s[nt][3] = fexp2(s[nt][3] - mn1);
            rs0 += s[nt][0] + s[nt][1];
            rs1 += s[nt][2] + s[nt][3];
        }
        rs0 += __shfl_xor_sync(0xffffffffu, rs0, 1);
        rs0 += __shfl_xor_sync(0xffffffffu, rs0, 2);
        rs1 += __shfl_xor_sync(0xffffffffu, rs1, 1);
        rs1 += __shfl_xor_sync(0xffffffffu, rs1, 2);
        l0 = l0 * a0 + rs0;
        l1 = l1 * a1 + rs1;
#pragma unroll
        for (int nt = 0; nt < 8; nt++) {
            o[nt][0] *= a0; o[nt][1] *= a0;
            o[nt][2] *= a1; o[nt][3] *= a1;
        }

        // ---- PV: P (regs -> A frag) x V (trans ldmatrix, split) ----
#pragma unroll
        for (int kc = 0; kc < 4; kc++) {
            uint32_t pa[4];
            pa[0] = h2u(__floats2half2_rn(s[2 * kc][0], s[2 * kc][1]));
            pa[1] = h2u(__floats2half2_rn(s[2 * kc][2], s[2 * kc][3]));
            pa[2] = h2u(__floats2half2_rn(s[2 * kc + 1][0], s[2 * kc + 1][1]));
            pa[3] = h2u(__floats2half2_rn(s[2 * kc + 1][2], s[2 * kc + 1][3]));
#pragma unroll
            for (int np = 0; np < 4; np++) {
                const uint32_t vaddr = smb + AV_H +
                    (uint32_t)((kc * 16 + (lane & 15)) * ASTR + np * 16 + (lane >> 4) * 8) * 2;
                uint32_t vh[4], vl[4];
                ldsm4t(vh, vaddr);
                ldsm4t(vl, vaddr + (AV_L - AV_H));
                mma_f16(o[2 * np], pa, vh[0], vh[1]);
                mma_f16(o[2 * np], pa, vl[0], vl[1]);
                mma_f16(o[2 * np + 1], pa, vh[2], vh[3]);
                mma_f16(o[2 * np + 1], pa, vl[2], vl[3]);
            }
        }
    }

    // epilogue: normalize, write fp32
    const float i0 = 1.f / l0, i1 = 1.f / l1;
    const int r0 = q0 + row0 + (lane >> 2);
#pragma unroll
    for (int nt = 0; nt < 8; nt++) {
        const int d = nt * 8 + 2 * (lane & 3);
        float2 v0 = {o[nt][0] * i0, o[nt][1] * i0};
        float2 v1 = {o[nt][2] * i1, o[nt][3] * i1};
        *(float2*)(O + ((size_t)b * SS + r0) * DD + h * DH + d) = v0;
        *(float2*)(O + ((size_t)b * SS + r0 + 8) * DD + h * DH + d) = v1;
    }
}

// ===========================================================================
extern "C" void kernel_launch(void* const* d_in, const int* in_sizes, int n_in,
                              void* d_out, int out_size)
{
    const float* x  = (const float*)d_in[0];
    // d_in[1] = causal mask (implicit in attention kernel)
    const float* WQ = (const float*)d_in[2];
    const float* bQ = (const float*)d_in[3];
    const float* WK = (const float*)d_in[4];
    const float* bK = (const float*)d_in[5];
    const float* WV = (const float*)d_in[6];
    const float* bV = (const float*)d_in[7];
    const float* WO = (const float*)d_in[8];
    const float* bO = (const float*)d_in[9];
    float* out = (float*)d_out;

    float *Qp, *Kp, *Vp, *Ap;
    cudaGetSymbolAddress((void**)&Qp, g_Q);
    cudaGetSymbolAddress((void**)&Kp, g_K);
    cudaGetSymbolAddress((void**)&Vp, g_V);
    cudaGetSymbolAddress((void**)&Ap, g_A);

    cudaFuncSetAttribute(gemm_split, cudaFuncAttributeMaxDynamicSharedMemorySize,
                         GEMM_SMEM);
    cudaFuncSetAttribute(attn_tc, cudaFuncAttributeMaxDynamicSharedMemorySize,
                         ATTN_SMEM);

    dim3 gg(DD / 128, MTOT / 128);   // (4, 64)
    gemm_split<<<gg, 256, GEMM_SMEM>>>(x, WQ, bQ, Qp);
    gemm_split<<<gg, 256, GEMM_SMEM>>>(x, WK, bK, Kp);
    gemm_split<<<gg, 256, GEMM_SMEM>>>(x, WV, bV, Vp);
    attn_tc<<<dim3(SS / 128, HH, BB), 256, ATTN_SMEM>>>(Qp, Kp, Vp, Ap);
    gemm_split<<<gg, 256, GEMM_SMEM>>>(Ap, WO, bO, out);
}